// round 16
// baseline (speedup 1.0000x reference)
#include <cuda_runtime.h>
#include <cuda_bf16.h>
#include <cuda_fp16.h>
#include <cstdint>

#define N_NODES 50000
#define N_REL   3
#define D       128
#define KTOT    (N_REL * D)          // 384
#define N_EDGES 600000
#define N_BUCK  (N_NODES * N_REL)    // 150000
#define CAP     64                   // slots per (dst,rel) bucket; P(deg>=64) < 1e-28
#define M_TILES ((N_NODES + 127) / 128)    // 391

// prep kernel (small): zero cursors + dtype detect
#define ZBLK 147          // 147*256 = 37632 >= 37500 int4

// fused fill kernel block ranges
#define FBLK_PER_REL ((N_EDGES / 8 + 255) / 256)   // 293
#define FBLK (N_REL * FBLK_PER_REL)                // 879
#define XBLK 1563         // x->fp16: 1563 blocks * 1024 float4 >= 1.6M
#define WBLK 192          // W^T fp16: 192*256 = 49152 = 3*128*128

// Scratch (device globals; no allocation allowed)
__device__ int    g_cursor[N_BUCK];                   // per-bucket edge count
__device__ int    g_esrc[(size_t)N_BUCK * CAP];       // bucketed src ids (38.4MB)
__device__ __half g_xh[(size_t)N_NODES * D];          // fp16 copy of x (12.8MB)
__device__ __half g_agg[(size_t)N_NODES * KTOT];      // fp16 agg [node][r*128+c]
__device__ __half g_wt[(size_t)D * KTOT];             // fp16 W^T [n][k]
__device__ int    g_idx32;                            // 1 if indices are int32

// ---------------------------------------------------------------------------
// Small prep: zero cursors | dtype detect (1 block)
// ---------------------------------------------------------------------------
__global__ __launch_bounds__(256) void prep_kernel(
    const unsigned int* __restrict__ src32,
    const unsigned int* __restrict__ dst32)
{
    const int bx = blockIdx.x;
    const int t  = threadIdx.x;

    if (bx < ZBLK) {
        int i = bx * 256 + t;
        if (i < N_BUCK / 4)
            ((int4*)g_cursor)[i] = make_int4(0, 0, 0, 0);
    } else {
        // dtype detect: int64 values < 2^31 => every odd 32-bit word is 0
        __shared__ int sh;
        if (t == 0) sh = 0;
        __syncthreads();
        unsigned int any = 0;
        for (int i = t; i < 4096; i += 256)
            any |= src32[2 * i + 1] | dst32[2 * i + 1];
        any = __reduce_or_sync(0xFFFFFFFFu, any);
        if ((t & 31) == 0 && any) atomicOr(&sh, 1);
        __syncthreads();
        if (t == 0) g_idx32 = sh ? 1 : 0;
    }
}

// ---------------------------------------------------------------------------
// Fused fill: edge bucket placement | x->fp16 | W^T fp16 (independent ranges
// run concurrently across SMs, hiding the conversions under the edge pass).
// ---------------------------------------------------------------------------
__global__ __launch_bounds__(256) void fill_kernel(
    const void* __restrict__ srcv,
    const void* __restrict__ dstv,
    const float* __restrict__ x,
    const float* __restrict__ W)
{
    const int bx = blockIdx.x;
    const int t  = threadIdx.x;

    if (bx < FBLK) {
        const int r  = bx / FBLK_PER_REL;
        const int qb = bx % FBLK_PER_REL;
        int q = qb * 256 + t;
        if (q >= N_EDGES / 8) return;
        if (g_idx32) {
            const int4* sp = (const int4*)srcv + (size_t)r * (N_EDGES / 4) + q * 2;
            const int4* dp = (const int4*)dstv + (size_t)r * (N_EDGES / 4) + q * 2;
            int4 sa = sp[0], sb2 = sp[1];
            int4 da = dp[0], db2 = dp[1];
            int ss[8] = { sa.x, sa.y, sa.z, sa.w, sb2.x, sb2.y, sb2.z, sb2.w };
            int dd[8] = { da.x, da.y, da.z, da.w, db2.x, db2.y, db2.z, db2.w };
#pragma unroll
            for (int j = 0; j < 8; j++) {
                if ((unsigned)ss[j] < N_NODES && (unsigned)dd[j] < N_NODES) {
                    int bkt = dd[j] * N_REL + r;
                    int pos = atomicAdd(&g_cursor[bkt], 1);
                    if (pos < CAP) g_esrc[(size_t)bkt * CAP + pos] = ss[j];
                }
            }
        } else {
            const long long* ps = (const long long*)srcv + (size_t)r * N_EDGES + q * 8;
            const long long* pd = (const long long*)dstv + (size_t)r * N_EDGES + q * 8;
#pragma unroll
            for (int j = 0; j < 8; j++) {
                long long s = ps[j], d = pd[j];
                if ((unsigned long long)s < N_NODES && (unsigned long long)d < N_NODES) {
                    int bkt = (int)d * N_REL + r;
                    int pos = atomicAdd(&g_cursor[bkt], 1);
                    if (pos < CAP) g_esrc[(size_t)bkt * CAP + pos] = (int)s;
                }
            }
        }
    } else if (bx < FBLK + XBLK) {
        // x -> fp16, 4 float4 per thread
        int base = (bx - FBLK) * 1024 + t;
        const int TOT = N_NODES * D / 4;   // 1.6M float4
#pragma unroll
        for (int j = 0; j < 4; j++) {
            int i = base + j * 256;
            if (i < TOT) {
                float4 v = ((const float4*)x)[i];
                __half2 h0 = __floats2half2_rn(v.x, v.y);
                __half2 h1 = __floats2half2_rn(v.z, v.w);
                uint2 u;
                u.x = *(uint32_t*)&h0;
                u.y = *(uint32_t*)&h1;
                ((uint2*)g_xh)[i] = u;
            }
        }
    } else {
        int i = (bx - FBLK - XBLK) * 256 + t;   // 0..49151 exactly
        int r   = i / (D * D);
        int rem = i % (D * D);
        int din = rem / D;
        int n   = rem % D;
        g_wt[(size_t)n * KTOT + r * D + din] = __float2half(W[i]);
    }
}

// ---------------------------------------------------------------------------
// Aggregate: one warp per bucket; uint4 gathers cover 2 rows per warp-load
// (half-warps on rows j/j+1) -> half the gather instructions. fp32 accum,
// cross-half-warp shfl reduction, fp16 agg output by lanes 0-15.
// ---------------------------------------------------------------------------
__device__ __forceinline__ void acc8(float* f, uint4 u) {
    float2 a = __half22float2(*(__half2*)&u.x);
    float2 b = __half22float2(*(__half2*)&u.y);
    float2 c = __half22float2(*(__half2*)&u.z);
    float2 d = __half22float2(*(__half2*)&u.w);
    f[0] += a.x; f[1] += a.y; f[2] += b.x; f[3] += b.y;
    f[4] += c.x; f[5] += c.y; f[6] += d.x; f[7] += d.y;
}

__global__ __launch_bounds__(256) void aggregate_kernel() {
    const int warp = blockIdx.x * 8 + (threadIdx.x >> 5);
    const int lane = threadIdx.x & 31;
    if (warp >= N_BUCK) return;

    int n = g_cursor[warp];
    if (n > CAP) n = CAP;
    const int* el = g_esrc + (size_t)warp * CAP;
    const uint4* x4 = (const uint4*)g_xh;   // 8 halves per uint4, row stride 16

    const int half = lane >> 4;   // 0/1: which of the 2 rows this lane serves
    const int li   = lane & 15;   // column chunk within the row

    // lane-parallel index load: one LDG covers the first 32 indices
    int idx0 = (lane < n) ? el[lane] : 0;

    float f[8] = {0.f, 0.f, 0.f, 0.f, 0.f, 0.f, 0.f, 0.f};
    int nn = (n < 32) ? n : 32;
    int j = 0;
    for (; j + 8 <= nn; j += 8) {     // 4 pairs, 4 loads in flight
        uint4 u[4];
#pragma unroll
        for (int p = 0; p < 4; p++) {
            int s = __shfl_sync(0xFFFFFFFFu, idx0, j + 2 * p + half);
            u[p] = __ldg(x4 + (size_t)s * 16 + li);
        }
#pragma unroll
        for (int p = 0; p < 4; p++) acc8(f, u[p]);
    }
    for (; j < nn; j += 2) {
        int row = j + half;
        int sr  = (row < 31) ? row : 31;
        int s   = __shfl_sync(0xFFFFFFFFu, idx0, sr);
        if (row < nn) acc8(f, __ldg(x4 + (size_t)s * 16 + li));
    }

    if (n > 32) {   // warp-uniform, rare (P ~ 1e-7)
        int idx1 = (32 + lane < n) ? el[32 + lane] : 0;
        for (int r2 = 32; r2 < n; r2 += 2) {
            int row = r2 + half;
            int sr  = (row - 32 < 31) ? row - 32 : 31;
            int s   = __shfl_sync(0xFFFFFFFFu, idx1, sr);
            if (row < n) acc8(f, __ldg(x4 + (size_t)s * 16 + li));
        }
    }

    // combine the two half-warp row-sums
#pragma unroll
    for (int q = 0; q < 8; q++)
        f[q] += __shfl_down_sync(0xFFFFFFFFu, f[q], 16);

    if (half == 0) {
        __half2 h0 = __floats2half2_rn(f[0], f[1]);
        __half2 h1 = __floats2half2_rn(f[2], f[3]);
        __half2 h2 = __floats2half2_rn(f[4], f[5]);
        __half2 h3 = __floats2half2_rn(f[6], f[7]);
        uint4 o;
        o.x = *(uint32_t*)&h0;
        o.y = *(uint32_t*)&h1;
        o.z = *(uint32_t*)&h2;
        o.w = *(uint32_t*)&h3;
        ((uint4*)g_agg)[(size_t)warp * 16 + li] = o;
    }
}

// ---------------------------------------------------------------------------
// Tensor-core GEMM: single-pass fp16 mma.sync + ldmatrix + 3-stage cp.async.
// out = agg(fp16) @ W^T(fp16), fp32 accum, + degree-weighted bias.
// ---------------------------------------------------------------------------
#define TS 40                        // smem tile row stride (fp16) = 80 bytes
#define TILE_B (128 * TS * 2)        // 10240 bytes per tile
#define STAGE_B (2 * TILE_B)         // 20480 bytes per stage (A, B)
#define NSTAGE 3
#define SM_BIAS (NSTAGE * STAGE_B)   // 61440
#define SM_TOTAL (SM_BIAS + KTOT * 4)  // 62976

#define LDSM_X4(r0_, r1_, r2_, r3_, addr_)                                  \
    asm volatile(                                                           \
        "ldmatrix.sync.aligned.m8n8.x4.shared.b16 {%0,%1,%2,%3}, [%4];"     \
        : "=r"(r0_), "=r"(r1_), "=r"(r2_), "=r"(r3_) : "r"(addr_))

#define MMA_F16(dv, av, b0_, b1_)                                           \
    asm volatile(                                                           \
        "mma.sync.aligned.m16n8k16.row.col.f32.f16.f16.f32 "                \
        "{%0,%1,%2,%3}, {%4,%5,%6,%7}, {%8,%9}, {%0,%1,%2,%3};"             \
        : "+f"(dv[0]), "+f"(dv[1]), "+f"(dv[2]), "+f"(dv[3])                \
        : "r"(av[0]), "r"(av[1]), "r"(av[2]), "r"(av[3]),                   \
          "r"(b0_), "r"(b1_))

#define CP16(saddr_, gptr_)                                                 \
    asm volatile("cp.async.cg.shared.global [%0], [%1], 16;"                \
                 :: "r"(saddr_), "l"(gptr_))

__global__ __launch_bounds__(256, 2) void gemm_mma_kernel(const float* __restrict__ b,
                                                          float* __restrict__ out)
{
    extern __shared__ char smem[];
    const uint32_t uS = (uint32_t)__cvta_generic_to_shared(smem);

    const int tid  = threadIdx.x;
    const int wid  = tid >> 5;
    const int lane = tid & 31;
    const int gid  = lane >> 2;   // 0..7
    const int tig  = lane & 3;    // 0..3
    const int wm   = wid & 3;     // 4 m-tiles of 32
    const int wn   = wid >> 2;    // 2 n-tiles of 64
    const int row0 = blockIdx.x * 128;

    float* sb = (float*)(smem + SM_BIAS);
    for (int i = tid; i < KTOT; i += 256) sb[i] = b[i];

    // Per-thread tile-load coordinates (2 chunks of 512 uint4 per tile)
    int ldso[2];          // smem byte offset within a tile
    size_t gaA[2];        // clamped A row base (element index)
    size_t gaB[2];        // B row base
#pragma unroll
    for (int l = 0; l < 2; l++) {
        int i   = tid + l * 256;
        int row = i >> 2;
        int ch  = i & 3;
        ldso[l] = (row * TS + ch * 8) * 2;
        int grow = row0 + row;
        if (grow > N_NODES - 1) grow = N_NODES - 1; // clamp: OOB rows never stored
        gaA[l] = (size_t)grow * KTOT + ch * 8;
        gaB[l] = (size_t)row * KTOT + ch * 8;
    }

    // ldmatrix lane-address offsets (bytes within a tile)
    const int lm  = lane >> 3;
    const int lr  = lane & 7;
    const int a_off = ((wm * 32 + (lm & 1) * 8 + lr) * TS + (lm >> 1) * 8) * 2;
    const int b_off = ((wn * 64 + (lm >> 1) * 8 + lr) * TS + (lm & 1) * 8) * 2;

    float acc[2][8][4];
#pragma unroll
    for (int i = 0; i < 2; i++)
#pragma unroll
        for (int j = 0; j < 8; j++)
#pragma unroll
            for (int q = 0; q < 4; q++) acc[i][j][q] = 0.f;

    // ---- prologue: issue stages 0 and 1 ----
#pragma unroll
    for (int s = 0; s < 2; s++) {
        uint32_t st = uS + s * STAGE_B;
        int kn = s * 32;
#pragma unroll
        for (int l = 0; l < 2; l++) {
            CP16(st + ldso[l],          g_agg + gaA[l] + kn);
            CP16(st + TILE_B + ldso[l], g_wt  + gaB[l] + kn);
        }
        asm volatile("cp.async.commit_group;");
    }

    int slot = 0;   // stage slot of current k-tile
    for (int kt = 0; kt < 12; kt++) {
        if (kt < 11) asm volatile("cp.async.wait_group 1;");
        else         asm volatile("cp.async.wait_group 0;");
        __syncthreads();

        // issue k-tile kt+2 into slot (slot+2)%3
        if (kt < 10) {
            int sl2 = slot + 2; if (sl2 >= NSTAGE) sl2 -= NSTAGE;
            uint32_t st = uS + sl2 * STAGE_B;
            int kn = (kt + 2) * 32;
#pragma unroll
            for (int l = 0; l < 2; l++) {
                CP16(st + ldso[l],          g_agg + gaA[l] + kn);
                CP16(st + TILE_B + ldso[l], g_wt  + gaB[l] + kn);
            }
            asm volatile("cp.async.commit_group;");
        }

        const uint32_t st = uS + slot * STAGE_B;
        const uint32_t uA = st, uB = st + TILE_B;

        // ---- compute current tile: 2 k16 sub-chunks ----
#pragma unroll
        for (int ks = 0; ks < 32; ks += 16) {
            uint32_t ah[2][4];
#pragma unroll
            for (int i = 0; i < 2; i++) {
                uint32_t ao = (uint32_t)(a_off + (i * 16 * TS + ks) * 2);
                LDSM_X4(ah[i][0], ah[i][1], ah[i][2], ah[i][3], uA + ao);
            }
#pragma unroll
            for (int jpp = 0; jpp < 2; jpp++) {
                uint32_t bh[2][4];
#pragma unroll
                for (int p = 0; p < 2; p++) {
                    int jp = jpp * 2 + p;
                    uint32_t bo = (uint32_t)(b_off + (jp * 16 * TS + ks) * 2);
                    LDSM_X4(bh[p][0], bh[p][1], bh[p][2], bh[p][3], uB + bo);
                }
#pragma unroll
                for (int p = 0; p < 2; p++) {
                    int j0 = (jpp * 2 + p) * 2;
#pragma unroll
                    for (int i = 0; i < 2; i++) {
                        MMA_F16(acc[i][j0],     ah[i], bh[p][0], bh[p][1]);
                        MMA_F16(acc[i][j0 + 1], ah[i], bh[p][2], bh[p][3]);
                    }
                }
            }
        }

        slot++; if (slot >= NSTAGE) slot -= NSTAGE;
    }

    // ---- epilogue: bias via degree counts (true counts), write out ----
#pragma unroll
    for (int i = 0; i < 2; i++) {
#pragma unroll
        for (int half = 0; half < 2; half++) {
            int row = row0 + wm * 32 + i * 16 + gid + half * 8;
            if (row >= N_NODES) continue;
            float c0 = (float)g_cursor[row * N_REL + 0];
            float c1 = (float)g_cursor[row * N_REL + 1];
            float c2 = (float)g_cursor[row * N_REL + 2];
#pragma unroll
            for (int j = 0; j < 8; j++) {
                int col = wn * 64 + j * 8 + 2 * tig;
                float2 v;
                v.x = acc[i][j][half * 2 + 0]
                    + c0 * sb[col]     + c1 * sb[128 + col]     + c2 * sb[256 + col];
                v.y = acc[i][j][half * 2 + 1]
                    + c0 * sb[col + 1] + c1 * sb[128 + col + 1] + c2 * sb[256 + col + 1];
                *(float2*)(out + (size_t)row * D + col) = v;
            }
        }
    }
}

// ---------------------------------------------------------------------------
// Launch: 4 kernels total
// ---------------------------------------------------------------------------
extern "C" void kernel_launch(void* const* d_in, const int* in_sizes, int n_in,
                              void* d_out, int out_size)
{
    const float* x   = (const float*)d_in[0];
    const float* W   = (const float*)d_in[1];
    const float* b   = (const float*)d_in[2];
    const void*  src = d_in[3];
    const void*  dst = d_in[4];
    float*       out = (float*)d_out;

    static int smem_set = 0;
    if (!smem_set) {
        cudaFuncSetAttribute(gemm_mma_kernel,
                             cudaFuncAttributeMaxDynamicSharedMemorySize, SM_TOTAL);
        smem_set = 1;
    }

    prep_kernel<<<ZBLK + 1, 256>>>((const unsigned int*)src,
                                   (const unsigned int*)dst);

    fill_kernel<<<FBLK + XBLK + WBLK, 256>>>(src, dst, x, W);

    aggregate_kernel<<<(N_BUCK + 7) / 8, 256>>>();

    gemm_mma_kernel<<<M_TILES, 256, SM_TOTAL>>>(b, out);
}

// round 17
// speedup vs baseline: 1.0516x; 1.0516x over previous
#include <cuda_runtime.h>
#include <cuda_bf16.h>
#include <cuda_fp16.h>
#include <cstdint>

#define N_NODES 50000
#define N_REL   3
#define D       128
#define KTOT    (N_REL * D)          // 384
#define N_EDGES 600000
#define N_BUCK  (N_NODES * N_REL)    // 150000
#define CAP     64                   // slots per (dst,rel) bucket; P(deg>=64) < 1e-28
#define M_TILES ((N_NODES + 127) / 128)    // 391

// prep kernel block ranges
#define ZBLK 147    // zero cursors: 147*256 = 37632 >= 37500 int4
#define WBLK 192    // w^T fp16: 192*256 = 49152 = 3*128*128
#define XBLK 6250   // x->fp16: 6250*256*4 = 6.4M elements

// Scratch (device globals; no allocation allowed)
__device__ int    g_cursor[N_BUCK];                   // per-bucket edge count
__device__ int    g_esrc[(size_t)N_BUCK * CAP];       // bucketed src ids (38.4MB)
__device__ __half g_xh[(size_t)N_NODES * D];          // fp16 copy of x (12.8MB)
__device__ __half g_agg[(size_t)N_NODES * KTOT];      // fp16 agg [node][r*128+c]
__device__ __half g_wt[(size_t)D * KTOT];             // fp16 W^T [n][k]
__device__ int    g_idx32;                            // 1 if indices are int32

// ---------------------------------------------------------------------------
// Fused prep: zero cursors | W^T fp16 | x->fp16 | dtype detect (1 blk)
// ---------------------------------------------------------------------------
__global__ __launch_bounds__(256) void prep_kernel(
    const float* __restrict__ x,
    const float* __restrict__ W,
    const unsigned int* __restrict__ src32,
    const unsigned int* __restrict__ dst32)
{
    const int bx = blockIdx.x;
    const int t  = threadIdx.x;

    if (bx < ZBLK) {
        int i = bx * 256 + t;
        if (i < N_BUCK / 4)
            ((int4*)g_cursor)[i] = make_int4(0, 0, 0, 0);
    } else if (bx < ZBLK + WBLK) {
        int i = (bx - ZBLK) * 256 + t;        // 0..49151 exactly
        int r   = i / (D * D);
        int rem = i % (D * D);
        int din = rem / D;
        int n   = rem % D;
        g_wt[(size_t)n * KTOT + r * D + din] = __float2half(W[i]);
    } else if (bx < ZBLK + WBLK + XBLK) {
        int i = (bx - ZBLK - WBLK) * 256 + t;  // x in float4 units
        float4 v = ((const float4*)x)[i];
        __half2 h0 = __floats2half2_rn(v.x, v.y);
        __half2 h1 = __floats2half2_rn(v.z, v.w);
        uint2 u;
        u.x = *(uint32_t*)&h0;
        u.y = *(uint32_t*)&h1;
        ((uint2*)g_xh)[i] = u;
    } else {
        // dtype detect: int64 values < 2^31 => every odd 32-bit word is 0
        __shared__ int sh;
        if (t == 0) sh = 0;
        __syncthreads();
        unsigned int any = 0;
        for (int i = t; i < 4096; i += 256)
            any |= src32[2 * i + 1] | dst32[2 * i + 1];
        any = __reduce_or_sync(0xFFFFFFFFu, any);
        if ((t & 31) == 0 && any) atomicOr(&sh, 1);
        __syncthreads();
        if (t == 0) g_idx32 = sh ? 1 : 0;
    }
}

// ---------------------------------------------------------------------------
// Fill: direct fixed-capacity bucket placement, 8 edges per thread.
// ---------------------------------------------------------------------------
__global__ __launch_bounds__(256) void fill_kernel(const void* __restrict__ srcv,
                                                   const void* __restrict__ dstv) {
    const int r = blockIdx.y;
    int q = blockIdx.x * 256 + threadIdx.x;
    if (q >= N_EDGES / 8) return;
    if (g_idx32) {
        const int4* sp = (const int4*)srcv + (size_t)r * (N_EDGES / 4) + q * 2;
        const int4* dp = (const int4*)dstv + (size_t)r * (N_EDGES / 4) + q * 2;
        int4 sa = sp[0], sb2 = sp[1];
        int4 da = dp[0], db2 = dp[1];
        int ss[8] = { sa.x, sa.y, sa.z, sa.w, sb2.x, sb2.y, sb2.z, sb2.w };
        int dd[8] = { da.x, da.y, da.z, da.w, db2.x, db2.y, db2.z, db2.w };
#pragma unroll
        for (int j = 0; j < 8; j++) {
            if ((unsigned)ss[j] < N_NODES && (unsigned)dd[j] < N_NODES) {
                int bkt = dd[j] * N_REL + r;
                int pos = atomicAdd(&g_cursor[bkt], 1);
                if (pos < CAP) g_esrc[(size_t)bkt * CAP + pos] = ss[j];
            }
        }
    } else {
        const long long* ps = (const long long*)srcv + (size_t)r * N_EDGES + q * 8;
        const long long* pd = (const long long*)dstv + (size_t)r * N_EDGES + q * 8;
#pragma unroll
        for (int j = 0; j < 8; j++) {
            long long s = ps[j], d = pd[j];
            if ((unsigned long long)s < N_NODES && (unsigned long long)d < N_NODES) {
                int bkt = (int)d * N_REL + r;
                int pos = atomicAdd(&g_cursor[bkt], 1);
                if (pos < CAP) g_esrc[(size_t)bkt * CAP + pos] = (int)s;
            }
        }
    }
}

// ---------------------------------------------------------------------------
// Aggregate: one warp per bucket. Indices loaded lane-parallel (one LDG),
// broadcast via shfl; gathers unrolled x8 for MLP. fp32 accumulate,
// emit fp16 agg.
// ---------------------------------------------------------------------------
__device__ __forceinline__ void acc_row(float4& acc, uint2 u) {
    float2 f0 = __half22float2(*(__half2*)&u.x);
    float2 f1 = __half22float2(*(__half2*)&u.y);
    acc.x += f0.x; acc.y += f0.y; acc.z += f1.x; acc.w += f1.y;
}

__global__ __launch_bounds__(256) void aggregate_kernel() {
    const int warp = blockIdx.x * 8 + (threadIdx.x >> 5);
    const int lane = threadIdx.x & 31;
    if (warp >= N_BUCK) return;

    int n = g_cursor[warp];
    if (n > CAP) n = CAP;
    const int* el = g_esrc + (size_t)warp * CAP;
    const uint2* x2 = (const uint2*)g_xh;   // 4 halves per uint2, row stride 32

    // lane-parallel index load: one LDG covers the first 32 indices
    int idx0 = (lane < n) ? el[lane] : 0;

    float4 acc = make_float4(0.f, 0.f, 0.f, 0.f);
    int nn = (n < 32) ? n : 32;
    int i = 0;
    for (; i + 8 <= nn; i += 8) {
        int s[8];
#pragma unroll
        for (int j = 0; j < 8; j++)
            s[j] = __shfl_sync(0xFFFFFFFFu, idx0, i + j);
        uint2 u[8];
#pragma unroll
        for (int j = 0; j < 8; j++)
            u[j] = __ldg(x2 + (size_t)s[j] * 32 + lane);
#pragma unroll
        for (int j = 0; j < 8; j++) acc_row(acc, u[j]);
    }
    if (i + 4 <= nn) {
        int s[4];
#pragma unroll
        for (int j = 0; j < 4; j++)
            s[j] = __shfl_sync(0xFFFFFFFFu, idx0, i + j);
        uint2 u[4];
#pragma unroll
        for (int j = 0; j < 4; j++)
            u[j] = __ldg(x2 + (size_t)s[j] * 32 + lane);
#pragma unroll
        for (int j = 0; j < 4; j++) acc_row(acc, u[j]);
        i += 4;
    }
    for (; i < nn; i++) {
        int s = __shfl_sync(0xFFFFFFFFu, idx0, i);
        acc_row(acc, __ldg(x2 + (size_t)s * 32 + lane));
    }

    if (n > 32) {   // warp-uniform branch; rare (P(deg>32) ~ 1e-7)
        int idx1 = (32 + lane < n) ? el[32 + lane] : 0;
        for (int j2 = 32; j2 < n; j2++) {
            int s = __shfl_sync(0xFFFFFFFFu, idx1, j2 - 32);
            acc_row(acc, __ldg(x2 + (size_t)s * 32 + lane));
        }
    }

    __half2 h0 = __floats2half2_rn(acc.x, acc.y);
    __half2 h1 = __floats2half2_rn(acc.z, acc.w);
    uint2 u;
    u.x = *(uint32_t*)&h0;
    u.y = *(uint32_t*)&h1;
    ((uint2*)g_agg)[(size_t)warp * 32 + lane] = u;
}

// ---------------------------------------------------------------------------
// Tensor-core GEMM: single-pass fp16 mma.sync + ldmatrix + 4-stage cp.async.
// out = agg(fp16) @ W^T(fp16), fp32 accum, + degree-weighted bias.
// Steady state: wait_group 2 -> stage being computed was issued 3 iters ago.
// ---------------------------------------------------------------------------
#define TS 40                        // smem tile row stride (fp16) = 80 bytes
#define TILE_B (128 * TS * 2)        // 10240 bytes per tile
#define STAGE_B (2 * TILE_B)         // 20480 bytes per stage (A, B)
#define NSTAGE 4
#define SM_BIAS (NSTAGE * STAGE_B)   // 81920
#define SM_TOTAL (SM_BIAS + KTOT * 4)  // 83456

#define LDSM_X4(r0_, r1_, r2_, r3_, addr_)                                  \
    asm volatile(                                                           \
        "ldmatrix.sync.aligned.m8n8.x4.shared.b16 {%0,%1,%2,%3}, [%4];"     \
        : "=r"(r0_), "=r"(r1_), "=r"(r2_), "=r"(r3_) : "r"(addr_))

#define MMA_F16(dv, av, b0_, b1_)                                           \
    asm volatile(                                                           \
        "mma.sync.aligned.m16n8k16.row.col.f32.f16.f16.f32 "                \
        "{%0,%1,%2,%3}, {%4,%5,%6,%7}, {%8,%9}, {%0,%1,%2,%3};"             \
        : "+f"(dv[0]), "+f"(dv[1]), "+f"(dv[2]), "+f"(dv[3])                \
        : "r"(av[0]), "r"(av[1]), "r"(av[2]), "r"(av[3]),                   \
          "r"(b0_), "r"(b1_))

#define CP16(saddr_, gptr_)                                                 \
    asm volatile("cp.async.cg.shared.global [%0], [%1], 16;"                \
                 :: "r"(saddr_), "l"(gptr_))

__global__ __launch_bounds__(256, 2) void gemm_mma_kernel(const float* __restrict__ b,
                                                          float* __restrict__ out)
{
    extern __shared__ char smem[];
    const uint32_t uS = (uint32_t)__cvta_generic_to_shared(smem);

    const int tid  = threadIdx.x;
    const int wid  = tid >> 5;
    const int lane = tid & 31;
    const int gid  = lane >> 2;   // 0..7
    const int tig  = lane & 3;    // 0..3
    const int wm   = wid & 3;     // 4 m-tiles of 32
    const int wn   = wid >> 2;    // 2 n-tiles of 64
    const int row0 = blockIdx.x * 128;

    float* sb = (float*)(smem + SM_BIAS);
    for (int i = tid; i < KTOT; i += 256) sb[i] = b[i];

    // Per-thread tile-load coordinates (2 chunks of 512 uint4 per tile)
    int ldso[2];          // smem byte offset within a tile
    size_t gaA[2];        // clamped A row base (element index)
    size_t gaB[2];        // B row base
#pragma unroll
    for (int l = 0; l < 2; l++) {
        int i   = tid + l * 256;
        int row = i >> 2;
        int ch  = i & 3;
        ldso[l] = (row * TS + ch * 8) * 2;
        int grow = row0 + row;
        if (grow > N_NODES - 1) grow = N_NODES - 1; // clamp: OOB rows never stored
        gaA[l] = (size_t)grow * KTOT + ch * 8;
        gaB[l] = (size_t)row * KTOT + ch * 8;
    }

    // ldmatrix lane-address offsets (bytes within a tile)
    const int lm  = lane >> 3;
    const int lr  = lane & 7;
    const int a_off = ((wm * 32 + (lm & 1) * 8 + lr) * TS + (lm >> 1) * 8) * 2;
    const int b_off = ((wn * 64 + (lm >> 1) * 8 + lr) * TS + (lm & 1) * 8) * 2;

    float acc[2][8][4];
#pragma unroll
    for (int i = 0; i < 2; i++)
#pragma unroll
        for (int j = 0; j < 8; j++)
#pragma unroll
            for (int q = 0; q < 4; q++) acc[i][j][q] = 0.f;

    // ---- prologue: issue stages 0, 1, 2 ----
#pragma unroll
    for (int s = 0; s < 3; s++) {
        uint32_t st = uS + s * STAGE_B;
        int kn = s * 32;
#pragma unroll
        for (int l = 0; l < 2; l++) {
            CP16(st + ldso[l],          g_agg + gaA[l] + kn);
            CP16(st + TILE_B + ldso[l], g_wt  + gaB[l] + kn);
        }
        asm volatile("cp.async.commit_group;");
    }

    int slot = 0;   // stage slot of current k-tile
    for (int kt = 0; kt < 12; kt++) {
        // groups issued so far = 3 + min(kt,9); need groups 0..kt complete
        if (kt <= 9)       asm volatile("cp.async.wait_group 2;");
        else if (kt == 10) asm volatile("cp.async.wait_group 1;");
        else               asm volatile("cp.async.wait_group 0;");
        __syncthreads();

        // issue k-tile kt+3 into slot (slot+3)%4 (its readers passed the sync)
        if (kt < 9) {
            int sl3 = slot + 3; if (sl3 >= NSTAGE) sl3 -= NSTAGE;
            uint32_t st = uS + sl3 * STAGE_B;
            int kn = (kt + 3) * 32;
#pragma unroll
            for (int l = 0; l < 2; l++) {
                CP16(st + ldso[l],          g_agg + gaA[l] + kn);
                CP16(st + TILE_B + ldso[l], g_wt  + gaB[l] + kn);
            }
            asm volatile("cp.async.commit_group;");
        }

        const uint32_t st = uS + slot * STAGE_B;
        const uint32_t uA = st, uB = st + TILE_B;

        // ---- compute current tile: 2 k16 sub-chunks ----
#pragma unroll
        for (int ks = 0; ks < 32; ks += 16) {
            uint32_t ah[2][4];
#pragma unroll
            for (int i = 0; i < 2; i++) {
                uint32_t ao = (uint32_t)(a_off + (i * 16 * TS + ks) * 2);
                LDSM_X4(ah[i][0], ah[i][1], ah[i][2], ah[i][3], uA + ao);
            }
#pragma unroll
            for (int jpp = 0; jpp < 2; jpp++) {
                uint32_t bh[2][4];
#pragma unroll
                for (int p = 0; p < 2; p++) {
                    int jp = jpp * 2 + p;
                    uint32_t bo = (uint32_t)(b_off + (jp * 16 * TS + ks) * 2);
                    LDSM_X4(bh[p][0], bh[p][1], bh[p][2], bh[p][3], uB + bo);
                }
#pragma unroll
                for (int p = 0; p < 2; p++) {
                    int j0 = (jpp * 2 + p) * 2;
#pragma unroll
                    for (int i = 0; i < 2; i++) {
                        MMA_F16(acc[i][j0],     ah[i], bh[p][0], bh[p][1]);
                        MMA_F16(acc[i][j0 + 1], ah[i], bh[p][2], bh[p][3]);
                    }
                }
            }
        }

        slot++; if (slot >= NSTAGE) slot -= NSTAGE;
    }

    // ---- epilogue: bias via degree counts (true counts), write out ----
#pragma unroll
    for (int i = 0; i < 2; i++) {
#pragma unroll
        for (int half = 0; half < 2; half++) {
            int row = row0 + wm * 32 + i * 16 + gid + half * 8;
            if (row >= N_NODES) continue;
            float c0 = (float)g_cursor[row * N_REL + 0];
            float c1 = (float)g_cursor[row * N_REL + 1];
            float c2 = (float)g_cursor[row * N_REL + 2];
#pragma unroll
            for (int j = 0; j < 8; j++) {
                int col = wn * 64 + j * 8 + 2 * tig;
                float2 v;
                v.x = acc[i][j][half * 2 + 0]
                    + c0 * sb[col]     + c1 * sb[128 + col]     + c2 * sb[256 + col];
                v.y = acc[i][j][half * 2 + 1]
                    + c0 * sb[col + 1] + c1 * sb[128 + col + 1] + c2 * sb[256 + col + 1];
                *(float2*)(out + (size_t)row * D + col) = v;
            }
        }
    }
}

// ---------------------------------------------------------------------------
// Launch: 4 kernels total
// ---------------------------------------------------------------------------
extern "C" void kernel_launch(void* const* d_in, const int* in_sizes, int n_in,
                              void* d_out, int out_size)
{
    const float* x   = (const float*)d_in[0];
    const float* W   = (const float*)d_in[1];
    const float* b   = (const float*)d_in[2];
    const void*  src = d_in[3];
    const void*  dst = d_in[4];
    float*       out = (float*)d_out;

    static int smem_set = 0;
    if (!smem_set) {
        cudaFuncSetAttribute(gemm_mma_kernel,
                             cudaFuncAttributeMaxDynamicSharedMemorySize, SM_TOTAL);
        smem_set = 1;
    }

    prep_kernel<<<ZBLK + WBLK + XBLK + 1, 256>>>(x, W,
                                                 (const unsigned int*)src,
                                                 (const unsigned int*)dst);

    dim3 egrid((N_EDGES / 8 + 255) / 256, N_REL);   // 8 edges per thread
    fill_kernel<<<egrid, 256>>>(src, dst);

    aggregate_kernel<<<(N_BUCK + 7) / 8, 256>>>();

    gemm_mma_kernel<<<M_TILES, 256, SM_TOTAL>>>(b, out);
}